// round 1
// baseline (speedup 1.0000x reference)
#include <cuda_runtime.h>
#include <math.h>

// Problem constants
#define NUM_E   8
#define BATCH   4
#define CCAP    1024
#define DMODEL  1024
#define DFF     4096

// Tiling
#define BM 128
#define BN 128
#define BK 32
#define PK 36   // BK + 4 padding (conflict-free fragment gathers: addr%32 == lane)

// 512 MB scratch for the intermediate h = gelu(x@W1^T + b1), fp32.
// (device global array: sanctioned scratch mechanism, no allocation APIs)
__device__ float g_h[134217728];  // 4*8*1024*4096

__device__ __forceinline__ unsigned f2tf32(float x) {
    unsigned y;
    asm("cvt.rna.tf32.f32 %0, %1;" : "=r"(y) : "f"(x));
    return y;
}

__device__ __forceinline__ void mma_tf32(float acc[4], const unsigned a[4], const unsigned b[2]) {
    asm volatile(
        "mma.sync.aligned.m16n8k8.row.col.f32.tf32.tf32.f32 "
        "{%0,%1,%2,%3}, {%4,%5,%6,%7}, {%8,%9}, {%0,%1,%2,%3};\n"
        : "+f"(acc[0]), "+f"(acc[1]), "+f"(acc[2]), "+f"(acc[3])
        : "r"(a[0]), "r"(a[1]), "r"(a[2]), "r"(a[3]),
          "r"(b[0]), "r"(b[1]));
}

__device__ __forceinline__ float gelu_exact(float x) {
    return 0.5f * x * (1.0f + erff(x * 0.7071067811865476f));
}

// NT GEMM: O[grp][m][n] = sum_k A[grp][m][k] * W[e][n][k]  (+bias[e][n], opt gelu)
// A: per-group [M, K] contiguous; W: per-expert [N, K] row-major (torch Linear layout).
template<int M, int N, int K, bool DO_GELU>
__global__ void __launch_bounds__(256, 1)
gemm_nt(const float* __restrict__ A0, size_t aStride,
        const float* __restrict__ W0,
        const float* __restrict__ bias0,
        float* __restrict__ O0, size_t oStride)
{
    __shared__ unsigned As[BM][PK];
    __shared__ unsigned Bs[BN][PK];

    const int grp = blockIdx.z;          // b * NUM_E + e
    const int e   = grp & (NUM_E - 1);

    const float* A    = A0 + (size_t)grp * aStride;
    const float* W    = W0 + (size_t)e * N * K;
    const float* bias = bias0 + (size_t)e * N;
    float*       O    = O0 + (size_t)grp * oStride;

    const int bm = blockIdx.y * BM;
    const int bn = blockIdx.x * BN;

    const int tid  = threadIdx.x;
    const int rowL = tid >> 3;   // 0..31 : tile row group
    const int colv = tid & 7;    // 0..7  : float4 index along K

    const float* Ag = A + (size_t)(bm + rowL) * K + colv * 4;
    const float* Wg = W + (size_t)(bn + rowL) * K + colv * 4;

    float4 ra[4], rb[4];

    auto load_tile = [&](int kt) {
        const size_t koff = (size_t)kt * BK;
        #pragma unroll
        for (int i = 0; i < 4; ++i) {
            ra[i] = *reinterpret_cast<const float4*>(Ag + (size_t)(i * 32) * K + koff);
            rb[i] = *reinterpret_cast<const float4*>(Wg + (size_t)(i * 32) * K + koff);
        }
    };

    auto store_tile = [&]() {
        #pragma unroll
        for (int i = 0; i < 4; ++i) {
            uint4 va = make_uint4(f2tf32(ra[i].x), f2tf32(ra[i].y),
                                  f2tf32(ra[i].z), f2tf32(ra[i].w));
            *reinterpret_cast<uint4*>(&As[rowL + i * 32][colv * 4]) = va;
            uint4 vb = make_uint4(f2tf32(rb[i].x), f2tf32(rb[i].y),
                                  f2tf32(rb[i].z), f2tf32(rb[i].w));
            *reinterpret_cast<uint4*>(&Bs[rowL + i * 32][colv * 4]) = vb;
        }
    };

    // Warp layout: 8 warps as 2x4; each warp owns a 64x32 sub-tile.
    const int warpId = tid >> 5;
    const int lane   = tid & 31;
    const int wr = warpId >> 2;   // 0..1
    const int wc = warpId & 3;    // 0..3
    const int g  = lane >> 2;     // groupID  0..7
    const int tq = lane & 3;      // quad tid 0..3

    float acc[4][4][4];
    #pragma unroll
    for (int mi = 0; mi < 4; ++mi)
        #pragma unroll
        for (int ni = 0; ni < 4; ++ni)
            #pragma unroll
            for (int c = 0; c < 4; ++c)
                acc[mi][ni][c] = 0.0f;

    const int nk = K / BK;
    load_tile(0);

    #pragma unroll 1
    for (int kt = 0; kt < nk; ++kt) {
        store_tile();
        __syncthreads();
        if (kt + 1 < nk) load_tile(kt + 1);   // overlap next gmem load with compute

        #pragma unroll
        for (int kk = 0; kk < BK; kk += 8) {
            unsigned af[4][4], bf[4][2];
            #pragma unroll
            for (int mi = 0; mi < 4; ++mi) {
                const int r = wr * 64 + mi * 16 + g;
                af[mi][0] = As[r][kk + tq];
                af[mi][1] = As[r + 8][kk + tq];
                af[mi][2] = As[r][kk + tq + 4];
                af[mi][3] = As[r + 8][kk + tq + 4];
            }
            #pragma unroll
            for (int ni = 0; ni < 4; ++ni) {
                const int cn = wc * 32 + ni * 8 + g;
                bf[ni][0] = Bs[cn][kk + tq];
                bf[ni][1] = Bs[cn][kk + tq + 4];
            }
            #pragma unroll
            for (int mi = 0; mi < 4; ++mi)
                #pragma unroll
                for (int ni = 0; ni < 4; ++ni)
                    mma_tf32(acc[mi][ni], af[mi], bf[ni]);
        }
        __syncthreads();
    }

    // Epilogue: +bias, optional exact gelu, store fp32.
    #pragma unroll
    for (int mi = 0; mi < 4; ++mi) {
        const int r0 = bm + wr * 64 + mi * 16 + g;
        #pragma unroll
        for (int ni = 0; ni < 4; ++ni) {
            const int c0 = bn + wc * 32 + ni * 8 + tq * 2;
            const float bv0 = bias[c0];
            const float bv1 = bias[c0 + 1];
            float v00 = acc[mi][ni][0] + bv0;
            float v01 = acc[mi][ni][1] + bv1;
            float v10 = acc[mi][ni][2] + bv0;
            float v11 = acc[mi][ni][3] + bv1;
            if (DO_GELU) {
                v00 = gelu_exact(v00); v01 = gelu_exact(v01);
                v10 = gelu_exact(v10); v11 = gelu_exact(v11);
            }
            O[(size_t)r0 * N + c0]           = v00;
            O[(size_t)r0 * N + c0 + 1]       = v01;
            O[(size_t)(r0 + 8) * N + c0]     = v10;
            O[(size_t)(r0 + 8) * N + c0 + 1] = v11;
        }
    }
}

extern "C" void kernel_launch(void* const* d_in, const int* in_sizes, int n_in,
                              void* d_out, int out_size)
{
    const float* inputs = (const float*)d_in[0];  // [4, 8192, 1024]
    const float* w1     = (const float*)d_in[1];  // [8, 4096, 1024]
    const float* b1     = (const float*)d_in[2];  // [8, 4096]
    const float* w2     = (const float*)d_in[3];  // [8, 1024, 4096]
    const float* b2     = (const float*)d_in[4];  // [8, 1024]
    float*       out    = (float*)d_out;          // [4, 8192, 1024]

    void* hptr = nullptr;
    cudaGetSymbolAddress(&hptr, g_h);
    float* h = (float*)hptr;

    // GEMM1 + gelu: h[grp][c][f], grp = b*8+e  (32 groups, M=1024, N=4096, K=1024)
    {
        dim3 grid(DFF / BN, CCAP / BM, BATCH * NUM_E);
        gemm_nt<CCAP, DFF, DMODEL, true><<<grid, 256>>>(
            inputs, (size_t)CCAP * DMODEL, w1, b1, h, (size_t)CCAP * DFF);
    }
    // GEMM2: out[grp][c][d]  (32 groups, M=1024, N=1024, K=4096)
    {
        dim3 grid(DMODEL / BN, CCAP / BM, BATCH * NUM_E);
        gemm_nt<CCAP, DMODEL, DFF, false><<<grid, 256>>>(
            h, (size_t)CCAP * DFF, w2, b2, out, (size_t)CCAP * DMODEL);
    }
}

// round 5
// speedup vs baseline: 1.4057x; 1.4057x over previous
#include <cuda_runtime.h>
#include <math.h>
#include <cstdint>

#define NUM_E   8
#define BATCH   4
#define CCAP    1024
#define DMODEL  1024
#define DFF     4096

// CTA tile 128x256, BK=32; 8 warps in 2x4 grid, each warp 64x64.
#define BM 128
#define BN 256
#define BK 32

// smem stages in fragment-native layout:
// A: 32 blocks (mb 0..7, kb 0..3) of 132 words (128 data + 4 pad)
// B: 128 blocks (nb 0..31, kb 0..3) of 66 words (64 data + 2 pad)
#define A_STAGE_W (32 * 132)          // 4224 words
#define B_STAGE_W (128 * 66)          // 8448 words
#define STAGE_W   (A_STAGE_W + B_STAGE_W)
#define SMEM_BYTES (2 * STAGE_W * 4)  // 101376 bytes

// 512 MB fp32 scratch for h = gelu(x@W1^T + b1)
__device__ float g_h[134217728];

__device__ __forceinline__ unsigned f2tf32(float x) {
    unsigned y;
    asm("cvt.rna.tf32.f32 %0, %1;" : "=r"(y) : "f"(x));
    return y;
}

__device__ __forceinline__ void mma_tf32(float acc[4], const unsigned a[4], const unsigned b[2]) {
    asm volatile(
        "mma.sync.aligned.m16n8k8.row.col.f32.tf32.tf32.f32 "
        "{%0,%1,%2,%3}, {%4,%5,%6,%7}, {%8,%9}, {%0,%1,%2,%3};\n"
        : "+f"(acc[0]), "+f"(acc[1]), "+f"(acc[2]), "+f"(acc[3])
        : "r"(a[0]), "r"(a[1]), "r"(a[2]), "r"(a[3]),
          "r"(b[0]), "r"(b[1]));
}

__device__ __forceinline__ float gelu_exact(float x) {
    return 0.5f * x * (1.0f + erff(x * 0.7071067811865476f));
}

// Grouped NT GEMM: O[grp][m][n] = sum_k A[grp][m][k] * W[e][n][k] + bias[e][n] (opt gelu)
template<int NTOT, int KTOT, bool GELU>
__global__ void __launch_bounds__(256, 1)
grouped_ffn(const float* __restrict__ A0, const float* __restrict__ W0,
            const float* __restrict__ bias0, float* __restrict__ O0)
{
    extern __shared__ unsigned sm[];

    const int tid  = threadIdx.x;
    const int wid  = tid >> 5;
    const int lane = tid & 31;
    const int wr   = wid >> 2;    // 0..1  (64-row slab)
    const int wc   = wid & 3;     // 0..3  (64-col slab)
    const int g    = lane >> 2;   // 0..7
    const int tq   = lane & 3;    // 0..3

    const int grp = blockIdx.z;
    const int e   = grp & (NUM_E - 1);
    const int bm  = blockIdx.y * BM;
    const int bn  = blockIdx.x * BN;

    const float* A = A0 + (size_t)grp * CCAP * KTOT + (size_t)bm * KTOT;
    const float* W = W0 + (size_t)e * NTOT * KTOT + (size_t)bn * KTOT;

    // gmem plan: thread t covers row (t>>3)+i*32, cols (t&7)*4 .. +3
    const int lr = tid >> 3;
    const int c0 = (tid & 7) * 4;
    const float* Ag = A + (size_t)lr * KTOT + c0;
    const float* Wg = W + (size_t)lr * KTOT + c0;

    // Fragment-layout STS offsets.
    // A element (r,c): block (r>>4, c>>3), word (g*4+tq)*4 + hi + 2*lo
    //   (hi = (r>>3)&1, lo = (c>>2)&1, tq = c&3) -> thread's 4 elems at +0,+4,+8,+12
    // B element (n,c): block (n>>3, c>>3), word (g*4+tq)*2 + lo -> +0,+2,+4,+6
    int aoff[4], boff[8];
    {
        const int kb = c0 >> 3;
        const int lo = (c0 >> 2) & 1;
        #pragma unroll
        for (int i = 0; i < 4; ++i) {
            const int r = lr + i * 32;
            aoff[i] = ((r >> 4) * 4 + kb) * 132 + (r & 7) * 16 + ((r >> 3) & 1) + 2 * lo;
        }
        #pragma unroll
        for (int i = 0; i < 8; ++i) {
            const int r = lr + i * 32;
            boff[i] = ((r >> 3) * 4 + kb) * 66 + (r & 7) * 8 + lo;
        }
    }

    float4 ra[4], rb[8];

    auto LDG_TILE = [&](int kt) {
        const size_t k0 = (size_t)kt * BK;
        #pragma unroll
        for (int i = 0; i < 4; ++i)
            ra[i] = *reinterpret_cast<const float4*>(Ag + (size_t)(i * 32) * KTOT + k0);
        #pragma unroll
        for (int i = 0; i < 8; ++i)
            rb[i] = *reinterpret_cast<const float4*>(Wg + (size_t)(i * 32) * KTOT + k0);
    };

    auto STS_TILE = [&](int s) {
        unsigned* ab = sm + s * STAGE_W;
        unsigned* bb = ab + A_STAGE_W;
        #pragma unroll
        for (int i = 0; i < 4; ++i) {
            ab[aoff[i] + 0]  = f2tf32(ra[i].x);
            ab[aoff[i] + 4]  = f2tf32(ra[i].y);
            ab[aoff[i] + 8]  = f2tf32(ra[i].z);
            ab[aoff[i] + 12] = f2tf32(ra[i].w);
        }
        #pragma unroll
        for (int i = 0; i < 8; ++i) {
            bb[boff[i] + 0] = f2tf32(rb[i].x);
            bb[boff[i] + 2] = f2tf32(rb[i].y);
            bb[boff[i] + 4] = f2tf32(rb[i].z);
            bb[boff[i] + 6] = f2tf32(rb[i].w);
        }
    };

    float acc[4][8][4];
    #pragma unroll
    for (int mi = 0; mi < 4; ++mi)
        #pragma unroll
        for (int ni = 0; ni < 8; ++ni)
            #pragma unroll
            for (int c = 0; c < 4; ++c)
                acc[mi][ni][c] = 0.0f;

    auto COMPUTE = [&](int s) {
        const unsigned* ab = sm + s * STAGE_W + (wr * 16) * 132 + lane * 4;
        const unsigned* bb = sm + s * STAGE_W + A_STAGE_W + (wc * 32) * 66 + lane * 2;
        #pragma unroll
        for (int kb = 0; kb < 4; ++kb) {
            unsigned af[4][4], bf[8][2];
            #pragma unroll
            for (int mi = 0; mi < 4; ++mi) {
                const uint4 v = *reinterpret_cast<const uint4*>(ab + (mi * 4 + kb) * 132);
                af[mi][0] = v.x; af[mi][1] = v.y; af[mi][2] = v.z; af[mi][3] = v.w;
            }
            #pragma unroll
            for (int ni = 0; ni < 8; ++ni) {
                const uint2 v = *reinterpret_cast<const uint2*>(bb + (ni * 4 + kb) * 66);
                bf[ni][0] = v.x; bf[ni][1] = v.y;
            }
            #pragma unroll
            for (int mi = 0; mi < 4; ++mi)
                #pragma unroll
                for (int ni = 0; ni < 8; ++ni)
                    mma_tf32(acc[mi][ni], af[mi], bf[ni]);
        }
    };

    const int NK = KTOT / BK;

    LDG_TILE(0);
    STS_TILE(0);
    __syncthreads();

    #pragma unroll 1
    for (int kt = 0; kt < NK; ++kt) {
        const int s = kt & 1;
        if (kt + 1 < NK) LDG_TILE(kt + 1);   // gmem latency covered by compute
        COMPUTE(s);
        if (kt + 1 < NK) STS_TILE(s ^ 1);    // s^1 free: all warps passed sync(kt-1)
        __syncthreads();
    }

    // Epilogue: +bias, optional exact gelu, fp32 stores (float2 per point pair)
    const float* bias = bias0 + (size_t)e * NTOT + bn;
    float* O = O0 + (size_t)grp * CCAP * NTOT + bn;

    #pragma unroll
    for (int mi = 0; mi < 4; ++mi) {
        const int r0 = bm + wr * 64 + mi * 16 + g;
        #pragma unroll
        for (int ni = 0; ni < 8; ++ni) {
            const int cc = wc * 64 + ni * 8 + tq * 2;
            const float2 bv = *reinterpret_cast<const float2*>(bias + cc);
            float v00 = acc[mi][ni][0] + bv.x;
            float v01 = acc[mi][ni][1] + bv.y;
            float v10 = acc[mi][ni][2] + bv.x;
            float v11 = acc[mi][ni][3] + bv.y;
            if (GELU) {
                v00 = gelu_exact(v00); v01 = gelu_exact(v01);
                v10 = gelu_exact(v10); v11 = gelu_exact(v11);
            }
            *reinterpret_cast<float2*>(O + (size_t)r0 * NTOT + cc)       = make_float2(v00, v01);
            *reinterpret_cast<float2*>(O + (size_t)(r0 + 8) * NTOT + cc) = make_float2(v10, v11);
        }
    }
}

extern "C" void kernel_launch(void* const* d_in, const int* in_sizes, int n_in,
                              void* d_out, int out_size)
{
    const float* inputs = (const float*)d_in[0];  // [4, 8192, 1024]
    const float* w1     = (const float*)d_in[1];  // [8, 4096, 1024]
    const float* b1     = (const float*)d_in[2];  // [8, 4096]
    const float* w2     = (const float*)d_in[3];  // [8, 1024, 4096]
    const float* b2     = (const float*)d_in[4];  // [8, 1024]
    float*       out    = (float*)d_out;          // [4, 8192, 1024]

    void* hptr = nullptr;
    cudaGetSymbolAddress(&hptr, g_h);
    float* h = (float*)hptr;

    cudaFuncSetAttribute(grouped_ffn<DFF, DMODEL, true>,
                         cudaFuncAttributeMaxDynamicSharedMemorySize, SMEM_BYTES);
    cudaFuncSetAttribute(grouped_ffn<DMODEL, DFF, false>,
                         cudaFuncAttributeMaxDynamicSharedMemorySize, SMEM_BYTES);

    // GEMM1 + gelu: h[grp][c][f]  (32 groups, M=1024, N=4096, K=1024)
    {
        dim3 grid(DFF / BN, CCAP / BM, BATCH * NUM_E);
        grouped_ffn<DFF, DMODEL, true><<<grid, 256, SMEM_BYTES>>>(inputs, w1, b1, h);
    }
    // GEMM2: out[grp][c][d]  (32 groups, M=1024, N=1024, K=4096)
    {
        dim3 grid(DMODEL / BN, CCAP / BM, BATCH * NUM_E);
        grouped_ffn<DMODEL, DFF, false><<<grid, 256, SMEM_BYTES>>>(h, w2, b2, out);
    }
}